// round 4
// baseline (speedup 1.0000x reference)
#include <cuda_runtime.h>
#include <math.h>
#include <stdint.h>

// ---------------------------------------------------------------------------
// F = 8192 frames, chain:
//   X[2049,F] -> E1[1000,F] -> E[400,F] -> Gx[800,F] -> scan H[200,F]
//   Cat=[H;E][600,F] -> T1[800,F] -> T2[400,F] -> D[1000,F] -> out[2049,F]
// ---------------------------------------------------------------------------
#define FMAX 8192

__device__ float g_E1 [1000 * FMAX];
__device__ float g_Cat[ 600 * FMAX];
__device__ float g_Gx [ 800 * FMAX];
__device__ float g_T1 [ 800 * FMAX];
__device__ float g_T2 [ 400 * FMAX];
__device__ float g_D  [1000 * FMAX];
__device__ float g_bsum[800];

__device__ __forceinline__ float sigf(float x) { return 1.0f / (1.0f + expf(-x)); }
__device__ __forceinline__ float tanha(float x) {
    float y; asm("tanh.approx.f32 %0, %1;" : "=f"(y) : "f"(x)); return y;
}
__device__ __forceinline__ float siga(float x) {
    return 0.5f * tanha(0.5f * x) + 0.5f;
}

// packed f32x2 helpers
__device__ __forceinline__ void fma2(unsigned long long& acc,
                                     unsigned long long a, unsigned long long b) {
    asm("fma.rn.f32x2 %0, %1, %2, %0;" : "+l"(acc) : "l"(a), "l"(b));
}
__device__ __forceinline__ unsigned long long pack2(float x, float y) {
    unsigned long long v;
    asm("mov.b64 %0, {%1, %2};" : "=l"(v) : "f"(x), "f"(y));
    return v;
}
__device__ __forceinline__ void unpack2(float& lo, float& hi, unsigned long long v) {
    asm("mov.b64 {%0, %1}, %2;" : "=f"(lo), "=f"(hi) : "l"(v));
}
__device__ __forceinline__ uint32_t s2u(const void* p) {
    uint32_t a;
    asm("{ .reg .u64 t; cvta.to.shared.u64 t, %1; cvt.u32.u64 %0, t; }"
        : "=r"(a) : "l"(p));
    return a;
}

// ---------------------------------------------------------------------------
// GEMM: C[M,N] = act(A[M,K] @ B[K,N] + bias[M]); ACT: 0=lrelu, 1=none,
// 2=sigmoid()*X.  BM=128, BN=128, BK=16, 256 threads, 8x8 thread tile,
// f32x2 packed accumulators.  A loads vectorize only when K % 4 == 0
// (K=2049 rows are not 16B-aligned -> scalar fallback).
// ---------------------------------------------------------------------------
template <int ACT>
__global__ __launch_bounds__(256, 2) void gemm_kernel(
    const float* __restrict__ A, const float* __restrict__ B,
    const float* __restrict__ bias, float* __restrict__ C,
    int M, int N, int K, const float* __restrict__ X)
{
    constexpr int BM = 128, BN = 128, BK = 16;
    __shared__ float As[BK][BM];
    __shared__ float Bs[BK][BN];

    const int tid  = threadIdx.x;
    const int tx   = tid & 15;
    const int ty   = tid >> 4;
    const int row0 = ty << 3;
    const int col0 = tx << 3;
    const int m0   = blockIdx.y * BM;
    const int n0   = blockIdx.x * BN;

    const int am = tid & 127;          // A tile row
    const int ak = (tid >> 7) << 3;    // A k base (0 or 8)
    const int bk = tid >> 4;           // B tile k row
    const int bn = (tid & 15) << 3;    // B tile col

    const bool kvec = ((K & 3) == 0);  // uniform across block

    unsigned long long acc[8][4];
#pragma unroll
    for (int i = 0; i < 8; i++)
#pragma unroll
        for (int j = 0; j < 4; j++) acc[i][j] = 0ULL;

    for (int k0 = 0; k0 < K; k0 += BK) {
        // load A tile (transposed into SMEM)
#pragma unroll
        for (int h = 0; h < 2; h++) {
            int kb = ak + h * 4;
            float4 v = make_float4(0, 0, 0, 0);
            int gm = m0 + am;
            if (gm < M) {
                const float* src = A + (size_t)gm * K + k0 + kb;
                if (kvec && (k0 + kb + 3 < K)) {
                    v = *reinterpret_cast<const float4*>(src);
                } else {
                    float tmp[4];
#pragma unroll
                    for (int i = 0; i < 4; i++)
                        tmp[i] = (k0 + kb + i < K) ? src[i] : 0.0f;
                    v = make_float4(tmp[0], tmp[1], tmp[2], tmp[3]);
                }
            }
            As[kb + 0][am] = v.x;
            As[kb + 1][am] = v.y;
            As[kb + 2][am] = v.z;
            As[kb + 3][am] = v.w;
        }
        // load B tile (N always multiple of 128, rows 16B-aligned)
        {
            int kb2 = k0 + bk;
            float4 v0 = make_float4(0, 0, 0, 0), v1 = v0;
            if (kb2 < K) {
                const float4* src =
                    reinterpret_cast<const float4*>(B + (size_t)kb2 * N + n0 + bn);
                v0 = src[0];
                v1 = src[1];
            }
            *reinterpret_cast<float4*>(&Bs[bk][bn])     = v0;
            *reinterpret_cast<float4*>(&Bs[bk][bn + 4]) = v1;
        }
        __syncthreads();

#pragma unroll
        for (int kk = 0; kk < BK; kk++) {
            float4 a0 = *reinterpret_cast<const float4*>(&As[kk][row0]);
            float4 a1 = *reinterpret_cast<const float4*>(&As[kk][row0 + 4]);
            const ulonglong2* bp =
                reinterpret_cast<const ulonglong2*>(&Bs[kk][col0]);
            ulonglong2 bv0 = bp[0], bv1 = bp[1];
            unsigned long long b2[4] = {bv0.x, bv0.y, bv1.x, bv1.y};
            float ar[8] = {a0.x, a0.y, a0.z, a0.w, a1.x, a1.y, a1.z, a1.w};
#pragma unroll
            for (int i = 0; i < 8; i++) {
                unsigned long long ap = pack2(ar[i], ar[i]);
#pragma unroll
                for (int j = 0; j < 4; j++) fma2(acc[i][j], ap, b2[j]);
            }
        }
        __syncthreads();
    }

    // epilogue
#pragma unroll
    for (int i = 0; i < 8; i++) {
        int m = m0 + row0 + i;
        if (m >= M) continue;
        float bv = bias[m];
#pragma unroll
        for (int j = 0; j < 4; j++) {
            float lo, hi;
            unpack2(lo, hi, acc[i][j]);
            int n = n0 + col0 + 2 * j;
            size_t idx = (size_t)m * N + n;
            float v0 = lo + bv, v1 = hi + bv;
            if (ACT == 0) {
                v0 = (v0 >= 0.0f) ? v0 : 0.01f * v0;
                v1 = (v1 >= 0.0f) ? v1 : 0.01f * v1;
            } else if (ACT == 2) {
                v0 = sigf(v0) * X[idx];
                v1 = sigf(v1) * X[idx + 1];
            }
            *reinterpret_cast<float2*>(&C[idx]) = make_float2(v0, v1);
        }
    }
}

// ---------------------------------------------------------------------------
// bias sum: bsum = b_ih + b_hh
// ---------------------------------------------------------------------------
__global__ void bias_sum_kernel(const float* __restrict__ a,
                                const float* __restrict__ b,
                                float* __restrict__ out, int n)
{
    int i = blockIdx.x * blockDim.x + threadIdx.x;
    if (i < n) out[i] = a[i] + b[i];
}

// ---------------------------------------------------------------------------
// LSTM scan: 8-CTA cluster, interleaved gate partition.
//   CTA r owns h rows [25r, 25r+25) and the 100 gate rows (i,f,g,o at those
//   indices) feeding them -> no gate exchange; only the 25-float h slice is
//   pushed to all 8 CTAs per step via st.shared::cluster (proven-safe R0
//   primitive), one barrier.cluster per step.
//   W_hh slice lives in REGISTERS (512 threads, 4 per gate row, 32 packed
//   f32x2 regs each); h is read via broadcast LDS from a padded layout
//   (h[25s+o] at hbuf[32s+o], pads stay 0).  hbuf double buffered on t&1:
//   step-t writers target buffer (t+1)&1 while readers use t&1; the cluster
//   barrier at step end orders everything.
// ---------------------------------------------------------------------------
__global__ void __cluster_dims__(8, 1, 1) __launch_bounds__(512, 1)
lstm_scan_kernel(const float* __restrict__ Whh, const float* __restrict__ Gx,
                 float* __restrict__ Hout, int F)
{
    __shared__ __align__(16) float hbuf[2][256];   // padded h, double buffered
    __shared__ float sgate[100];

    const int tid  = threadIdx.x;
    const int rank = blockIdx.x;
    const int row  = tid >> 2;     // gate row within CTA (0..127; <100 valid)
    const int qi   = tid & 3;      // quarter of the 256 padded cols
    const bool valid = row < 100;
    const int g    = row / 25;     // gate index (i,f,g,o)
    const int j    = row % 25;
    const int grow = 200 * g + 25 * rank + j;   // global gate row

    // ---- load W_hh slice into registers (padded-col order) ----
    unsigned long long w[32];
#pragma unroll
    for (int k = 0; k < 32; k++) {
        float f0 = 0.0f, f1 = 0.0f;
        if (valid) {
            int c0 = qi * 64 + 2 * k;
            int s0 = c0 >> 5, o0 = c0 & 31;
            int c1 = c0 + 1;
            int s1 = c1 >> 5, o1 = c1 & 31;
            if (o0 < 25) f0 = Whh[(size_t)grow * 200 + s0 * 25 + o0];
            if (o1 < 25) f1 = Whh[(size_t)grow * 200 + s1 * 25 + o1];
        }
        w[k] = pack2(f0, f1);
    }

    // ---- init shared state ----
    if (tid < 256)                 hbuf[0][tid]       = 0.0f;
    else                           hbuf[1][tid - 256] = 0.0f;
    __syncthreads();

    // ---- per-peer DSMEM address of hbuf base (used by tid<25 only) ----
    const uint32_t hb_local = s2u(&hbuf[0][0]);
    uint32_t peer_h[8];
#pragma unroll
    for (int r = 0; r < 8; r++)
        asm("mapa.shared::cluster.u32 %0, %1, %2;"
            : "=r"(peer_h[r]) : "r"(hb_local), "r"(r));

    // zeroed buffers visible cluster-wide before first step
    asm volatile("barrier.cluster.arrive.aligned;" ::: "memory");
    asm volatile("barrier.cluster.wait.aligned;"   ::: "memory");

    const bool lead = (qi == 0) && valid;
    float c_state = 0.0f;                       // tid<25 owns c[25*rank+tid]
    float gx_cur = lead ? __ldg(&Gx[(size_t)grow * F]) : 0.0f;

    for (int t = 0; t < F; t++) {
        const int pb = t & 1;
        float gx_next = (lead && (t + 1 < F))
                          ? __ldg(&Gx[(size_t)grow * F + t + 1]) : 0.0f;

        // ---- GEMV: this thread's quarter of its gate row ----
        const ulonglong2* h4 = reinterpret_cast<const ulonglong2*>(
            &hbuf[pb][qi * 64]);
        unsigned long long acc = 0ULL;
#pragma unroll
        for (int k = 0; k < 16; k++) {
            ulonglong2 hv = h4[k];
            fma2(acc, w[2 * k],     hv.x);
            fma2(acc, w[2 * k + 1], hv.y);
        }
        float lo, hi;
        unpack2(lo, hi, acc);
        float s = lo + hi;
        s += __shfl_xor_sync(0xffffffffu, s, 1);
        s += __shfl_xor_sync(0xffffffffu, s, 2);
        if (lead) sgate[row] = s + gx_cur;
        gx_cur = gx_next;
        __syncthreads();

        // ---- LSTM update + push h slice to every CTA's next-buffer ----
        if (tid < 25) {
            float gi = sgate[tid];
            float gf = sgate[25 + tid];
            float gg = sgate[50 + tid];
            float go = sgate[75 + tid];
            float cn = siga(gf) * c_state + siga(gi) * tanha(gg);
            float hn = siga(go) * tanha(cn);
            c_state = cn;
            Hout[(size_t)(25 * rank + tid) * F + t] = hn;
            uint32_t off = (uint32_t)((((t + 1) & 1) * 256 + rank * 32 + tid) * 4);
#pragma unroll
            for (int r = 0; r < 8; r++)
                asm volatile("st.shared::cluster.f32 [%0], %1;"
                             :: "r"(peer_h[r] + off), "f"(hn) : "memory");
        }

        // one cluster barrier per step: orders remote stores + buffer swap
        asm volatile("barrier.cluster.arrive.aligned;" ::: "memory");
        asm volatile("barrier.cluster.wait.aligned;"   ::: "memory");
    }
}

// ---------------------------------------------------------------------------
// launch
// ---------------------------------------------------------------------------
extern "C" void kernel_launch(void* const* d_in, const int* in_sizes, int n_in,
                              void* d_out, int out_size)
{
    const float* mag = (const float*)d_in[0];
    const float* W1  = (const float*)d_in[1];
    const float* b1  = (const float*)d_in[2];
    const float* W2  = (const float*)d_in[3];
    const float* b2  = (const float*)d_in[4];
    const float* W3  = (const float*)d_in[5];
    const float* b3  = (const float*)d_in[6];
    const float* W4  = (const float*)d_in[7];
    const float* b4  = (const float*)d_in[8];
    const float* Wf1 = (const float*)d_in[9];
    const float* bf1 = (const float*)d_in[10];
    const float* Wf2 = (const float*)d_in[11];
    const float* bf2 = (const float*)d_in[12];
    const float* Wih = (const float*)d_in[13];
    const float* bih = (const float*)d_in[14];
    const float* Whh = (const float*)d_in[15];
    const float* bhh = (const float*)d_in[16];

    const int F = in_sizes[0] / 2049;
    float* out = (float*)d_out;

    float *E1, *Cat, *Gxp, *T1, *T2, *D, *bsum;
    cudaGetSymbolAddress((void**)&E1,   g_E1);
    cudaGetSymbolAddress((void**)&Cat,  g_Cat);
    cudaGetSymbolAddress((void**)&Gxp,  g_Gx);
    cudaGetSymbolAddress((void**)&T1,   g_T1);
    cudaGetSymbolAddress((void**)&T2,   g_T2);
    cudaGetSymbolAddress((void**)&D,    g_D);
    cudaGetSymbolAddress((void**)&bsum, g_bsum);

    float* E = Cat + (size_t)200 * F;   // E lives inside Cat rows 200..600

    dim3 blk(256);
    auto grid = [&](int M) { return dim3(F / 128, (M + 127) / 128); };

    bias_sum_kernel<<<4, 256>>>(bih, bhh, bsum, 800);

    // phase 1 (batched)
    gemm_kernel<0><<<grid(1000), blk>>>(W1,  mag, b1,   E1,  1000, F, 2049, nullptr);
    gemm_kernel<0><<<grid(400),  blk>>>(W2,  E1,  b2,   E,    400, F, 1000, nullptr);
    gemm_kernel<1><<<grid(800),  blk>>>(Wih, E,   bsum, Gxp,  800, F,  400, nullptr);

    // sequential LSTM scan -> Cat rows 0..200
    lstm_scan_kernel<<<8, 512>>>(Whh, Gxp, Cat, F);

    // phase 2 (batched)
    gemm_kernel<0><<<grid(800),  blk>>>(Wf1, Cat, bf1, T1,  800, F,  600, nullptr);
    gemm_kernel<0><<<grid(400),  blk>>>(Wf2, T1,  bf2, T2,  400, F,  800, nullptr);
    gemm_kernel<0><<<grid(1000), blk>>>(W3,  T2,  b3,  D,  1000, F,  400, nullptr);
    gemm_kernel<2><<<grid(2049), blk>>>(W4,  D,   b4,  out, 2049, F, 1000, mag);
}

// round 5
// speedup vs baseline: 3.3873x; 3.3873x over previous
#include <cuda_runtime.h>
#include <math.h>
#include <stdint.h>

// ---------------------------------------------------------------------------
// F = 8192 frames, chain:
//   X[2049,F] -> E1[1000,F] -> E[400,F] -> Gx[800,F] -> scan H[200,F]
//   Cat=[H;E][600,F] -> T1[800,F] -> T2[400,F] -> D[1000,F] -> out[2049,F]
// ---------------------------------------------------------------------------
#define FMAX 8192

__device__ float g_E1 [1000 * FMAX];
__device__ float g_Cat[ 600 * FMAX];
__device__ float g_Gx [ 800 * FMAX];
__device__ float g_T1 [ 800 * FMAX];
__device__ float g_T2 [ 400 * FMAX];
__device__ float g_D  [1000 * FMAX];
__device__ float g_bsum[800];

__device__ __forceinline__ float sigf(float x) { return 1.0f / (1.0f + expf(-x)); }
__device__ __forceinline__ float tanha(float x) {
    float y; asm("tanh.approx.f32 %0, %1;" : "=f"(y) : "f"(x)); return y;
}
__device__ __forceinline__ float siga(float x) {
    return 0.5f * tanha(0.5f * x) + 0.5f;
}

// packed f32x2 helpers
__device__ __forceinline__ void fma2(unsigned long long& acc,
                                     unsigned long long a, unsigned long long b) {
    asm("fma.rn.f32x2 %0, %1, %2, %0;" : "+l"(acc) : "l"(a), "l"(b));
}
__device__ __forceinline__ unsigned long long pack2(float x, float y) {
    unsigned long long v;
    asm("mov.b64 %0, {%1, %2};" : "=l"(v) : "f"(x), "f"(y));
    return v;
}
__device__ __forceinline__ void unpack2(float& lo, float& hi, unsigned long long v) {
    asm("mov.b64 {%0, %1}, %2;" : "=f"(lo), "=f"(hi) : "l"(v));
}
__device__ __forceinline__ uint32_t s2u(const void* p) {
    uint32_t a;
    asm("{ .reg .u64 t; cvta.to.shared.u64 t, %1; cvt.u32.u64 %0, t; }"
        : "=r"(a) : "l"(p));
    return a;
}

// ---------------------------------------------------------------------------
// GEMM: C[M,N] = act(A[M,K] @ B[K,N] + bias[M]); ACT: 0=lrelu, 1=none,
// 2=sigmoid()*X.  BM=128, BN=128, BK=16, 256 threads, 8x8 thread tile,
// f32x2 packed accumulators.  A loads vectorize only when K % 4 == 0.
// (unchanged from R4 — measured 187us on the Wih layer)
// ---------------------------------------------------------------------------
template <int ACT>
__global__ __launch_bounds__(256, 2) void gemm_kernel(
    const float* __restrict__ A, const float* __restrict__ B,
    const float* __restrict__ bias, float* __restrict__ C,
    int M, int N, int K, const float* __restrict__ X)
{
    constexpr int BM = 128, BN = 128, BK = 16;
    __shared__ float As[BK][BM];
    __shared__ float Bs[BK][BN];

    const int tid  = threadIdx.x;
    const int tx   = tid & 15;
    const int ty   = tid >> 4;
    const int row0 = ty << 3;
    const int col0 = tx << 3;
    const int m0   = blockIdx.y * BM;
    const int n0   = blockIdx.x * BN;

    const int am = tid & 127;
    const int ak = (tid >> 7) << 3;
    const int bk = tid >> 4;
    const int bn = (tid & 15) << 3;

    const bool kvec = ((K & 3) == 0);

    unsigned long long acc[8][4];
#pragma unroll
    for (int i = 0; i < 8; i++)
#pragma unroll
        for (int j = 0; j < 4; j++) acc[i][j] = 0ULL;

    for (int k0 = 0; k0 < K; k0 += BK) {
#pragma unroll
        for (int h = 0; h < 2; h++) {
            int kb = ak + h * 4;
            float4 v = make_float4(0, 0, 0, 0);
            int gm = m0 + am;
            if (gm < M) {
                const float* src = A + (size_t)gm * K + k0 + kb;
                if (kvec && (k0 + kb + 3 < K)) {
                    v = *reinterpret_cast<const float4*>(src);
                } else {
                    float tmp[4];
#pragma unroll
                    for (int i = 0; i < 4; i++)
                        tmp[i] = (k0 + kb + i < K) ? src[i] : 0.0f;
                    v = make_float4(tmp[0], tmp[1], tmp[2], tmp[3]);
                }
            }
            As[kb + 0][am] = v.x;
            As[kb + 1][am] = v.y;
            As[kb + 2][am] = v.z;
            As[kb + 3][am] = v.w;
        }
        {
            int kb2 = k0 + bk;
            float4 v0 = make_float4(0, 0, 0, 0), v1 = v0;
            if (kb2 < K) {
                const float4* src =
                    reinterpret_cast<const float4*>(B + (size_t)kb2 * N + n0 + bn);
                v0 = src[0];
                v1 = src[1];
            }
            *reinterpret_cast<float4*>(&Bs[bk][bn])     = v0;
            *reinterpret_cast<float4*>(&Bs[bk][bn + 4]) = v1;
        }
        __syncthreads();

#pragma unroll
        for (int kk = 0; kk < BK; kk++) {
            float4 a0 = *reinterpret_cast<const float4*>(&As[kk][row0]);
            float4 a1 = *reinterpret_cast<const float4*>(&As[kk][row0 + 4]);
            const ulonglong2* bp =
                reinterpret_cast<const ulonglong2*>(&Bs[kk][col0]);
            ulonglong2 bv0 = bp[0], bv1 = bp[1];
            unsigned long long b2[4] = {bv0.x, bv0.y, bv1.x, bv1.y};
            float ar[8] = {a0.x, a0.y, a0.z, a0.w, a1.x, a1.y, a1.z, a1.w};
#pragma unroll
            for (int i = 0; i < 8; i++) {
                unsigned long long ap = pack2(ar[i], ar[i]);
#pragma unroll
                for (int j = 0; j < 4; j++) fma2(acc[i][j], ap, b2[j]);
            }
        }
        __syncthreads();
    }

#pragma unroll
    for (int i = 0; i < 8; i++) {
        int m = m0 + row0 + i;
        if (m >= M) continue;
        float bv = bias[m];
#pragma unroll
        for (int j = 0; j < 4; j++) {
            float lo, hi;
            unpack2(lo, hi, acc[i][j]);
            int n = n0 + col0 + 2 * j;
            size_t idx = (size_t)m * N + n;
            float v0 = lo + bv, v1 = hi + bv;
            if (ACT == 0) {
                v0 = (v0 >= 0.0f) ? v0 : 0.01f * v0;
                v1 = (v1 >= 0.0f) ? v1 : 0.01f * v1;
            } else if (ACT == 2) {
                v0 = sigf(v0) * X[idx];
                v1 = sigf(v1) * X[idx + 1];
            }
            *reinterpret_cast<float2*>(&C[idx]) = make_float2(v0, v1);
        }
    }
}

// ---------------------------------------------------------------------------
// bias sum: bsum = b_ih + b_hh
// ---------------------------------------------------------------------------
__global__ void bias_sum_kernel(const float* __restrict__ a,
                                const float* __restrict__ b,
                                float* __restrict__ out, int n)
{
    int i = blockIdx.x * blockDim.x + threadIdx.x;
    if (i < n) out[i] = a[i] + b[i];
}

// ---------------------------------------------------------------------------
// LSTM scan v3: 8-CTA cluster, 128 threads (4 warps), NO barrier.cluster in
// the step loop.  CTA r owns h rows [25r,25r+25) and the 100 gate rows
// feeding them.  W_hh rows live whole in registers (1 thread per gate row,
// 100 f32x2 regs).  Per step:
//   GEMV (broadcast LDS of h) -> sgate -> __syncthreads
//   tid<25: LSTM update, push h to all 8 CTAs via st.shared::cluster
//   __syncthreads (BAR drains pending STS incl. DSMEM stores)
//   tid==0: one mbarrier.arrive on each peer's bars[t&1]   (count = 8)
//   all threads: try_wait(parity) on local bars[t&1]
// hbuf double-buffered on t&1; arrive-after-read makes the one-step-skew
// writer/reader race safe (a CTA reaching step t+2 can only overwrite a
// buffer every CTA finished reading at step t+1).
// ---------------------------------------------------------------------------
__global__ void __cluster_dims__(8, 1, 1) __launch_bounds__(128, 1)
lstm_scan_kernel(const float* __restrict__ Whh, const float* __restrict__ Gx,
                 float* __restrict__ Hout, int F)
{
    __shared__ __align__(16) float hbuf[2][200];   // h, double buffered
    __shared__ float sgate[100];
    __shared__ __align__(8) unsigned long long bars[2];

    const int tid  = threadIdx.x;
    const int rank = blockIdx.x;
    const bool valid = tid < 100;
    const int g    = tid / 25;                  // gate index (i,f,g,o)
    const int j    = tid % 25;
    const int grow = 200 * g + 25 * rank + j;   // global gate row

    // ---- whole W_hh row in registers: 100 packed f32x2 ----
    unsigned long long w[100];
    if (valid) {
        const float4* src = reinterpret_cast<const float4*>(Whh + (size_t)grow * 200);
#pragma unroll
        for (int k = 0; k < 50; k++) {
            float4 v = src[k];
            w[2 * k]     = pack2(v.x, v.y);
            w[2 * k + 1] = pack2(v.z, v.w);
        }
    } else {
#pragma unroll
        for (int k = 0; k < 100; k++) w[k] = 0ULL;
    }

    // ---- init shared state ----
    for (int i = tid; i < 400; i += 128)
        hbuf[i / 200][i % 200] = 0.0f;
    if (tid == 0) {
        asm volatile("mbarrier.init.shared.b64 [%0], 8;"
                     :: "r"(s2u(&bars[0])) : "memory");
        asm volatile("mbarrier.init.shared.b64 [%0], 8;"
                     :: "r"(s2u(&bars[1])) : "memory");
    }
    __syncthreads();

    // peer base addresses (mapa preserves intra-CTA offsets)
    const uint32_t hb_local  = s2u(&hbuf[0][0]);
    const uint32_t bar_delta = s2u(&bars[0]) - hb_local;
    uint32_t peer_h[8];
#pragma unroll
    for (int r = 0; r < 8; r++)
        asm("mapa.shared::cluster.u32 %0, %1, %2;"
            : "=r"(peer_h[r]) : "r"(hb_local), "r"(r));

    // barriers + zeroed buffers visible cluster-wide before first step
    asm volatile("barrier.cluster.arrive.aligned;" ::: "memory");
    asm volatile("barrier.cluster.wait.aligned;"   ::: "memory");

    float c_state = 0.0f;                       // tid<25 owns c[25*rank+tid]
    float gx_cur = valid ? __ldg(&Gx[(size_t)grow * F]) : 0.0f;
    int ph[2] = {0, 0};

    for (int t = 0; t < F; t++) {
        const int pb = t & 1;
        float gx_next = (valid && (t + 1 < F))
                          ? __ldg(&Gx[(size_t)grow * F + t + 1]) : 0.0f;

        // ---- GEMV: full 200-col row, 4 interleaved f32x2 accumulators ----
        if (valid) {
            const ulonglong2* h4 =
                reinterpret_cast<const ulonglong2*>(&hbuf[pb][0]);
            unsigned long long a0 = 0ULL, a1 = 0ULL, a2 = 0ULL, a3 = 0ULL;
#pragma unroll
            for (int k = 0; k < 25; k++) {
                ulonglong2 hA = h4[2 * k];
                ulonglong2 hB = h4[2 * k + 1];
                fma2(a0, w[4 * k],     hA.x);
                fma2(a1, w[4 * k + 1], hA.y);
                fma2(a2, w[4 * k + 2], hB.x);
                fma2(a3, w[4 * k + 3], hB.y);
            }
            float l0, h0, l1, h1, l2, h2, l3, h3;
            unpack2(l0, h0, a0); unpack2(l1, h1, a1);
            unpack2(l2, h2, a2); unpack2(l3, h3, a3);
            sgate[tid] = ((l0 + h0) + (l1 + h1)) + ((l2 + h2) + (l3 + h3))
                         + gx_cur;
        }
        gx_cur = gx_next;
        __syncthreads();

        // ---- LSTM update + push h slice to every CTA's next-buffer ----
        if (tid < 25) {
            float gi = sgate[tid];
            float gf = sgate[25 + tid];
            float gg = sgate[50 + tid];
            float go = sgate[75 + tid];
            float cn = siga(gf) * c_state + siga(gi) * tanha(gg);
            float hn = siga(go) * tanha(cn);
            c_state = cn;
            Hout[(size_t)(25 * rank + tid) * F + t] = hn;
            uint32_t off = (uint32_t)((((t + 1) & 1) * 200 + 25 * rank + tid) * 4);
#pragma unroll
            for (int r = 0; r < 8; r++)
                asm volatile("st.shared::cluster.f32 [%0], %1;"
                             :: "r"(peer_h[r] + off), "f"(hn) : "memory");
        }

        // BAR.SYNC drains pending STS (incl. DSMEM) before the signal
        __syncthreads();

        // ---- signal: one arrive per peer barrier (count 8) ----
        if (tid == 0) {
#pragma unroll
            for (int r = 0; r < 8; r++) {
                uint32_t ba = peer_h[r] + bar_delta + (uint32_t)(pb * 8);
                asm volatile("mbarrier.arrive.shared::cluster.b64 _, [%0];"
                             :: "r"(ba) : "memory");
            }
        }

        // ---- wait: local bars[pb], parity ph[pb] ----
        {
            const uint32_t ba = s2u(&bars[pb]);
            uint32_t done;
            asm volatile(
                "{\n\t.reg .pred p;\n\t"
                "mbarrier.try_wait.parity.acquire.cta.shared::cta.b64 p, [%1], %2;\n\t"
                "selp.b32 %0, 1, 0, p;\n\t}"
                : "=r"(done) : "r"(ba), "r"((uint32_t)ph[pb]) : "memory");
            if (!done) {
                asm volatile(
                    "{\n\t.reg .pred P1;\n\t"
                    "WL_%=:\n\t"
                    "mbarrier.try_wait.parity.acquire.cta.shared::cta.b64 P1, [%0], %1, 0x989680;\n\t"
                    "@P1 bra.uni WD_%=;\n\t"
                    "bra.uni WL_%=;\n\t"
                    "WD_%=:\n\t}"
                    :: "r"(ba), "r"((uint32_t)ph[pb]) : "memory");
            }
            ph[pb] ^= 1;
        }
    }

    // keep SMEM alive until every CTA's final stores/arrives landed
    asm volatile("barrier.cluster.arrive.aligned;" ::: "memory");
    asm volatile("barrier.cluster.wait.aligned;"   ::: "memory");
}

// ---------------------------------------------------------------------------
// launch
// ---------------------------------------------------------------------------
extern "C" void kernel_launch(void* const* d_in, const int* in_sizes, int n_in,
                              void* d_out, int out_size)
{
    const float* mag = (const float*)d_in[0];
    const float* W1  = (const float*)d_in[1];
    const float* b1  = (const float*)d_in[2];
    const float* W2  = (const float*)d_in[3];
    const float* b2  = (const float*)d_in[4];
    const float* W3  = (const float*)d_in[5];
    const float* b3  = (const float*)d_in[6];
    const float* W4  = (const float*)d_in[7];
    const float* b4  = (const float*)d_in[8];
    const float* Wf1 = (const float*)d_in[9];
    const float* bf1 = (const float*)d_in[10];
    const float* Wf2 = (const float*)d_in[11];
    const float* bf2 = (const float*)d_in[12];
    const float* Wih = (const float*)d_in[13];
    const float* bih = (const float*)d_in[14];
    const float* Whh = (const float*)d_in[15];
    const float* bhh = (const float*)d_in[16];

    const int F = in_sizes[0] / 2049;
    float* out = (float*)d_out;

    float *E1, *Cat, *Gxp, *T1, *T2, *D, *bsum;
    cudaGetSymbolAddress((void**)&E1,   g_E1);
    cudaGetSymbolAddress((void**)&Cat,  g_Cat);
    cudaGetSymbolAddress((void**)&Gxp,  g_Gx);
    cudaGetSymbolAddress((void**)&T1,   g_T1);
    cudaGetSymbolAddress((void**)&T2,   g_T2);
    cudaGetSymbolAddress((void**)&D,    g_D);
    cudaGetSymbolAddress((void**)&bsum, g_bsum);

    float* E = Cat + (size_t)200 * F;   // E lives inside Cat rows 200..600

    dim3 blk(256);
    auto grid = [&](int M) { return dim3(F / 128, (M + 127) / 128); };

    bias_sum_kernel<<<4, 256>>>(bih, bhh, bsum, 800);

    // phase 1 (batched)
    gemm_kernel<0><<<grid(1000), blk>>>(W1,  mag, b1,   E1,  1000, F, 2049, nullptr);
    gemm_kernel<0><<<grid(400),  blk>>>(W2,  E1,  b2,   E,    400, F, 1000, nullptr);
    gemm_kernel<1><<<grid(800),  blk>>>(Wih, E,   bsum, Gxp,  800, F,  400, nullptr);

    // sequential LSTM scan -> Cat rows 0..200
    lstm_scan_kernel<<<8, 128>>>(Whh, Gxp, Cat, F);

    // phase 2 (batched)
    gemm_kernel<0><<<grid(800),  blk>>>(Wf1, Cat, bf1, T1,  800, F,  600, nullptr);
    gemm_kernel<0><<<grid(400),  blk>>>(Wf2, T1,  bf2, T2,  400, F,  800, nullptr);
    gemm_kernel<0><<<grid(1000), blk>>>(W3,  T2,  b3,  D,  1000, F,  400, nullptr);
    gemm_kernel<2><<<grid(2049), blk>>>(W4,  D,   b4,  out, 2049, F, 1000, mag);
}